// round 6
// baseline (speedup 1.0000x reference)
#include <cuda_runtime.h>
#include <stdint.h>

#define NN 50000
#define NE 800000
#define NG 256
#define INDIM 300
#define HID 256

// ---------------- scratch (device globals; no allocation allowed) ----------------
__device__ __align__(16) float g_t[(size_t)NN * HID];   // transformed (h @ W)
__device__ __align__(16) float g_a[(size_t)NN * HID];   // aggregated output
__device__ float g_dinv[NN];
__device__ int   g_cnt[NN];
__device__ int   g_rowptr[NN + 1];
__device__ int   g_cursor[NN];
__device__ int   g_csr_src[NE];
__device__ float g_csr_w[NE];

// ---------------- graph preprocessing ----------------
__global__ void k_zero() {
    int i = blockIdx.x * blockDim.x + threadIdx.x;
    if (i < NN) g_cnt[i] = 0;
}

__global__ void k_hist(const int* __restrict__ ei) {
    int e = blockIdx.x * blockDim.x + threadIdx.x;
    if (e < NE) {
        int d = ei[NE + e];
        if (d >= 0 && d < NN) atomicAdd(&g_cnt[d], 1);
    }
}

// single-block: exclusive scan cnt->rowptr, plus dinv + cursor init
__global__ void k_scan() {
    const int CH = (NN + 1023) / 1024;  // 49
    __shared__ int part[1024];
    int t = threadIdx.x;
    int begin = t * CH;
    int end = begin + CH; if (end > NN) end = NN; if (begin > NN) begin = NN;
    int s = 0;
    for (int i = begin; i < end; i++) s += g_cnt[i];
    part[t] = s;
    __syncthreads();
    if (t == 0) {
        int run = 0;
        for (int i = 0; i < 1024; i++) { int v = part[i]; part[i] = run; run += v; }
    }
    __syncthreads();
    int run = part[t];
    for (int i = begin; i < end; i++) {
        int c = g_cnt[i];
        g_rowptr[i] = run; run += c;
        g_dinv[i] = rsqrtf((float)(c + 1));
        g_cursor[i] = 0;
    }
    if (t == 1023) g_rowptr[NN] = run;
}

__global__ void k_build(const int* __restrict__ ei) {
    int e = blockIdx.x * blockDim.x + threadIdx.x;
    if (e >= NE) return;
    int s = ei[e];
    int d = ei[NE + e];
    if (s < 0 || s >= NN || d < 0 || d >= NN) return;
    int pos = g_rowptr[d] + atomicAdd(&g_cursor[d], 1);
    g_csr_src[pos] = s;
    g_csr_w[pos] = g_dinv[s] * g_dinv[d];
}

// ---------------- tf32 tensor-core GEMM, 3-stage cp.async ring ----------------
__device__ __forceinline__ void cp16(uint32_t dst, const void* src, int srcbytes) {
    asm volatile("cp.async.cg.shared.global [%0], [%1], 16, %2;\n"
                 :: "r"(dst), "l"(src), "r"(srcbytes));
}
__device__ __forceinline__ void cp_commit() {
    asm volatile("cp.async.commit_group;\n");
}
__device__ __forceinline__ void cp_wait1() {
    asm volatile("cp.async.wait_group 1;\n");
}

// block tile 128x128, BK=16, 256 threads = 8 warps (4x2), warp tile 32x64
__global__ void __launch_bounds__(256) k_gemm_tc(const float* __restrict__ Aext, int use_ext,
                                                 const float* __restrict__ B, int K) {
    const float* A = use_ext ? Aext : (const float*)g_a;
    __shared__ uint32_t As[3][128][20];   // [buf][m][k]
    __shared__ uint32_t Bs[3][16][136];   // [buf][k][n]

    int bm = blockIdx.y * 128, bn = blockIdx.x * 128;
    int tid = threadIdx.x;
    int wid = tid >> 5, lane = tid & 31;
    int wr = wid >> 1, wc = wid & 1;
    int gid = lane >> 2, tig = lane & 3;

    int a_row0 = tid >> 2, a_kq0 = (tid & 3) << 2;
    int a_row1 = (tid + 256) >> 2, a_kq1 = ((tid + 256) & 3) << 2;
    int b_kk0 = tid >> 5, b_n40 = (tid & 31) << 2;
    int b_kk1 = (tid + 256) >> 5, b_n41 = ((tid + 256) & 31) << 2;

    float acc[2][8][4];
    #pragma unroll
    for (int i = 0; i < 2; i++)
        #pragma unroll
        for (int j = 0; j < 8; j++)
            #pragma unroll
            for (int l = 0; l < 4; l++) acc[i][j][l] = 0.f;

    int T = (K + 15) / 16;

    auto load_tile = [&](int tile, int buf) {
        int k0 = tile * 16;
        {
            int grow = bm + a_row0;
            int rem = K - (k0 + a_kq0);
            int bytes = (grow < NN && rem > 0) ? (rem >= 4 ? 16 : rem * 4) : 0;
            const float* src = (bytes > 0) ? (A + (size_t)grow * K + k0 + a_kq0) : A;
            cp16((uint32_t)__cvta_generic_to_shared(&As[buf][a_row0][a_kq0]), src, bytes);
        }
        {
            int grow = bm + a_row1;
            int rem = K - (k0 + a_kq1);
            int bytes = (grow < NN && rem > 0) ? (rem >= 4 ? 16 : rem * 4) : 0;
            const float* src = (bytes > 0) ? (A + (size_t)grow * K + k0 + a_kq1) : A;
            cp16((uint32_t)__cvta_generic_to_shared(&As[buf][a_row1][a_kq1]), src, bytes);
        }
        {
            int gk = k0 + b_kk0;
            int bytes = (gk < K) ? 16 : 0;
            const float* src = (bytes > 0) ? (B + (size_t)gk * 256 + bn + b_n40) : B;
            cp16((uint32_t)__cvta_generic_to_shared(&Bs[buf][b_kk0][b_n40]), src, bytes);
        }
        {
            int gk = k0 + b_kk1;
            int bytes = (gk < K) ? 16 : 0;
            const float* src = (bytes > 0) ? (B + (size_t)gk * 256 + bn + b_n41) : B;
            cp16((uint32_t)__cvta_generic_to_shared(&Bs[buf][b_kk1][b_n41]), src, bytes);
        }
    };

    load_tile(0, 0);
    cp_commit();
    if (T > 1) load_tile(1, 1);
    cp_commit();

    int buf = 0;
    for (int it = 0; it < T; it++) {
        cp_wait1();            // tile `it` resident
        __syncthreads();       // all warps done with the buffer being refilled next
        if (it + 2 < T) {
            int nbuf = buf + 2; if (nbuf >= 3) nbuf -= 3;
            load_tile(it + 2, nbuf);
        }
        cp_commit();

        #pragma unroll
        for (int ks = 0; ks < 16; ks += 8) {
            uint32_t a[2][4], b[8][2];
            #pragma unroll
            for (int mt = 0; mt < 2; mt++) {
                int r = wr * 32 + mt * 16;
                a[mt][0] = As[buf][r + gid][ks + tig];
                a[mt][1] = As[buf][r + gid + 8][ks + tig];
                a[mt][2] = As[buf][r + gid][ks + tig + 4];
                a[mt][3] = As[buf][r + gid + 8][ks + tig + 4];
            }
            #pragma unroll
            for (int nt = 0; nt < 8; nt++) {
                int c = wc * 64 + nt * 8 + gid;
                b[nt][0] = Bs[buf][ks + tig][c];
                b[nt][1] = Bs[buf][ks + tig + 4][c];
            }
            #pragma unroll
            for (int mt = 0; mt < 2; mt++)
                #pragma unroll
                for (int nt = 0; nt < 8; nt++) {
                    asm volatile(
                        "mma.sync.aligned.m16n8k8.row.col.f32.tf32.tf32.f32 "
                        "{%0,%1,%2,%3}, {%4,%5,%6,%7}, {%8,%9}, {%0,%1,%2,%3};"
                        : "+f"(acc[mt][nt][0]), "+f"(acc[mt][nt][1]),
                          "+f"(acc[mt][nt][2]), "+f"(acc[mt][nt][3])
                        : "r"(a[mt][0]), "r"(a[mt][1]), "r"(a[mt][2]), "r"(a[mt][3]),
                          "r"(b[nt][0]), "r"(b[nt][1]));
                }
        }
        buf++; if (buf >= 3) buf -= 3;
    }

    #pragma unroll
    for (int mt = 0; mt < 2; mt++) {
        #pragma unroll
        for (int nt = 0; nt < 8; nt++) {
            int r0 = bm + wr * 32 + mt * 16 + gid;
            int cc = bn + wc * 64 + nt * 8 + tig * 2;
            if (r0 < NN) {
                float2 v; v.x = acc[mt][nt][0]; v.y = acc[mt][nt][1];
                *(float2*)(g_t + (size_t)r0 * 256 + cc) = v;
            }
            if (r0 + 8 < NN) {
                float2 v; v.x = acc[mt][nt][2]; v.y = acc[mt][nt][3];
                *(float2*)(g_t + (size_t)(r0 + 8) * 256 + cc) = v;
            }
        }
    }
}

// ---------------- aggregation: 2 warps per node, 128 cols each, edge unroll x2 ----------------
__global__ void k_agg(const float* __restrict__ bias, int relu) {
    int gw = (blockIdx.x * blockDim.x + threadIdx.x) >> 5;
    int lane = threadIdx.x & 31;
    int n = gw >> 1;
    if (n >= NN) return;
    int col4 = ((gw & 1) << 5) + lane;   // float4 column index in [0,64)
    const float4* t4 = (const float4*)g_t;

    float dn = g_dinv[n];
    float sw = dn * dn;
    float4 a = __ldg(&t4[(size_t)n * 64 + col4]);
    a.x *= sw; a.y *= sw; a.z *= sw; a.w *= sw;

    int beg = g_rowptr[n], end = g_rowptr[n + 1];
    int i = beg;
    for (; i + 2 <= end; i += 2) {
        int s0 = g_csr_src[i],     s1 = g_csr_src[i + 1];
        float w0 = g_csr_w[i],     w1 = g_csr_w[i + 1];
        float4 v0 = __ldg(&t4[(size_t)s0 * 64 + col4]);
        float4 v1 = __ldg(&t4[(size_t)s1 * 64 + col4]);
        a.x += w0 * v0.x + w1 * v1.x;
        a.y += w0 * v0.y + w1 * v1.y;
        a.z += w0 * v0.z + w1 * v1.z;
        a.w += w0 * v0.w + w1 * v1.w;
    }
    if (i < end) {
        int s0 = g_csr_src[i];
        float w0 = g_csr_w[i];
        float4 v0 = __ldg(&t4[(size_t)s0 * 64 + col4]);
        a.x += w0 * v0.x; a.y += w0 * v0.y; a.z += w0 * v0.z; a.w += w0 * v0.w;
    }

    float4 b = ((const float4*)bias)[col4];
    a.x += b.x; a.y += b.y; a.z += b.z; a.w += b.w;
    if (relu) {
        a.x = fmaxf(a.x, 0.f); a.y = fmaxf(a.y, 0.f);
        a.z = fmaxf(a.z, 0.f); a.w = fmaxf(a.w, 0.f);
    }
    ((float4*)g_a)[(size_t)n * 64 + col4] = a;
}

// ---------------- fused mean-pool + classifier: one block per graph ----------------
__global__ void k_head(const int* __restrict__ batch,
                       const float* __restrict__ Wc1, const float* __restrict__ bc1,
                       const float* __restrict__ Wc2, const float* __restrict__ bc2,
                       const float* __restrict__ Wc3, const float* __restrict__ bc3,
                       float* __restrict__ out) {
    int g = blockIdx.x, t = threadIdx.x;
    __shared__ float p[256], q1[16], q2[64];
    __shared__ int slo, shi;
    if (t == 0) {
        int l = 0, r = NN;
        while (l < r) { int m = (l + r) >> 1; if (batch[m] < g) l = m + 1; else r = m; }
        slo = l;
        l = 0; r = NN;
        while (l < r) { int m = (l + r) >> 1; if (batch[m] < g + 1) l = m + 1; else r = m; }
        shi = l;
    }
    __syncthreads();
    int lo = slo, hi = shi;
    float s = 0.f;
    for (int n = lo; n < hi; n++) s += g_a[(size_t)n * 256 + t];
    int cnt = hi - lo;
    float inv = (cnt > 0) ? (1.0f / (float)cnt) : 1.0f;
    p[t] = s * inv;
    __syncthreads();

    float* o1 = out;
    float* o2 = out + 256 * 16;
    float* o3 = out + 256 * 16 + 256 * 64;

    if (t < 16) {
        float v = bc1[t];
        for (int k = 0; k < 256; k++) v += p[k] * Wc1[k * 16 + t];
        q1[t] = v;
        o1[g * 16 + t] = v;
    }
    __syncthreads();
    if (t == 0) {
        float m = q1[0];
        for (int i = 1; i < 16; i++) m = fmaxf(m, q1[i]);
        float sum = 0.f;
        for (int i = 0; i < 16; i++) { q1[i] = expf(q1[i] - m); sum += q1[i]; }
        float inv2 = 1.f / sum;
        for (int i = 0; i < 16; i++) q1[i] *= inv2;
    }
    __syncthreads();
    if (t < 64) {
        float v = bc2[t];
        for (int k = 0; k < 256; k++) v += p[k] * Wc2[k * 64 + t];
        for (int k = 0; k < 16; k++) v += q1[k] * Wc2[(256 + k) * 64 + t];
        q2[t] = v;
        o2[g * 64 + t] = v;
    }
    __syncthreads();
    if (t == 0) {
        float m = q2[0];
        for (int i = 1; i < 64; i++) m = fmaxf(m, q2[i]);
        float sum = 0.f;
        for (int i = 0; i < 64; i++) { q2[i] = expf(q2[i] - m); sum += q2[i]; }
        float inv2 = 1.f / sum;
        for (int i = 0; i < 64; i++) q2[i] *= inv2;
    }
    __syncthreads();
    {
        float v = bc3[t];
        for (int k = 0; k < 256; k++) v += p[k] * Wc3[k * 256 + t];
        for (int k = 0; k < 64; k++) v += q2[k] * Wc3[(256 + k) * 256 + t];
        o3[g * 256 + t] = v;
    }
}

// ---------------- launch ----------------
extern "C" void kernel_launch(void* const* d_in, const int* in_sizes, int n_in,
                              void* d_out, int out_size) {
    const float* x     = (const float*)d_in[0];
    const int*   ei    = (const int*)d_in[1];
    const int*   batch = (const int*)d_in[2];
    const float* W1 = (const float*)d_in[3],  *b1 = (const float*)d_in[4];
    const float* W2 = (const float*)d_in[5],  *b2 = (const float*)d_in[6];
    const float* W3 = (const float*)d_in[7],  *b3 = (const float*)d_in[8];
    const float* Wc1 = (const float*)d_in[9],  *bc1 = (const float*)d_in[10];
    const float* Wc2 = (const float*)d_in[11], *bc2 = (const float*)d_in[12];
    const float* Wc3 = (const float*)d_in[13], *bc3 = (const float*)d_in[14];
    float* out = (float*)d_out;

    k_zero<<<(NN + 255) / 256, 256>>>();
    k_hist<<<NE / 256, 256>>>(ei);
    k_scan<<<1, 1024>>>();
    k_build<<<NE / 256, 256>>>(ei);

    dim3 gg(2, (NN + 127) / 128);  // (2, 391)
    int agg_blocks = (NN * 2 * 32 + 255) / 256;  // 2 warps per node
    k_gemm_tc<<<gg, 256>>>(x, 1, W1, INDIM);
    k_agg<<<agg_blocks, 256>>>(b1, 1);
    k_gemm_tc<<<gg, 256>>>(nullptr, 0, W2, HID);
    k_agg<<<agg_blocks, 256>>>(b2, 1);
    k_gemm_tc<<<gg, 256>>>(nullptr, 0, W3, HID);
    k_agg<<<agg_blocks, 256>>>(b3, 0);

    k_head<<<NG, 256>>>(batch, Wc1, bc1, Wc2, bc2, Wc3, bc3, out);
}

// round 7
// speedup vs baseline: 1.0287x; 1.0287x over previous
#include <cuda_runtime.h>
#include <stdint.h>

#define NN 50000
#define NE 800000
#define NG 256
#define INDIM 300
#define HID 256

// ---------------- scratch (device globals; no allocation allowed) ----------------
__device__ __align__(16) float g_t[(size_t)NN * HID];   // transformed (h @ W)
__device__ __align__(16) float g_a[(size_t)NN * HID];   // aggregated output
__device__ float g_dinv[NN];
__device__ int   g_cnt[NN];
__device__ int   g_rowptr[NN + 1];
__device__ int   g_cursor[NN];
__device__ int   g_csr_src[NE];
__device__ float g_csr_w[NE];

// ---------------- graph preprocessing ----------------
__global__ void k_zero() {
    int i = blockIdx.x * blockDim.x + threadIdx.x;
    if (i < NN) g_cnt[i] = 0;
}

__global__ void k_hist(const int* __restrict__ ei) {
    int e = blockIdx.x * blockDim.x + threadIdx.x;
    if (e < NE) {
        int d = ei[NE + e];
        if (d >= 0 && d < NN) atomicAdd(&g_cnt[d], 1);
    }
}

// single-block: exclusive scan cnt->rowptr, plus dinv + cursor init
__global__ void k_scan() {
    const int CH = (NN + 1023) / 1024;  // 49
    __shared__ int part[1024];
    int t = threadIdx.x;
    int begin = t * CH;
    int end = begin + CH; if (end > NN) end = NN; if (begin > NN) begin = NN;
    int s = 0;
    for (int i = begin; i < end; i++) s += g_cnt[i];
    part[t] = s;
    __syncthreads();
    if (t == 0) {
        int run = 0;
        for (int i = 0; i < 1024; i++) { int v = part[i]; part[i] = run; run += v; }
    }
    __syncthreads();
    int run = part[t];
    for (int i = begin; i < end; i++) {
        int c = g_cnt[i];
        g_rowptr[i] = run; run += c;
        g_dinv[i] = rsqrtf((float)(c + 1));
        g_cursor[i] = 0;
    }
    if (t == 1023) g_rowptr[NN] = run;
}

__global__ void k_build(const int* __restrict__ ei) {
    int e = blockIdx.x * blockDim.x + threadIdx.x;
    if (e >= NE) return;
    int s = ei[e];
    int d = ei[NE + e];
    if (s < 0 || s >= NN || d < 0 || d >= NN) return;
    int pos = g_rowptr[d] + atomicAdd(&g_cursor[d], 1);
    g_csr_src[pos] = s;
    g_csr_w[pos] = g_dinv[s] * g_dinv[d];
}

// ---------------- tf32 tensor-core GEMM, 2-stage cp.async pipeline (R5-proven) ----------------
__device__ __forceinline__ void cp16(uint32_t dst, const void* src, int srcbytes) {
    asm volatile("cp.async.cg.shared.global [%0], [%1], 16, %2;\n"
                 :: "r"(dst), "l"(src), "r"(srcbytes));
}
__device__ __forceinline__ void cp_commit() {
    asm volatile("cp.async.commit_group;\n");
}
__device__ __forceinline__ void cp_wait1() {
    asm volatile("cp.async.wait_group 1;\n");
}

// block tile 128x128, BK=16, 256 threads = 8 warps (4x2), warp tile 32x64
__global__ void __launch_bounds__(256) k_gemm_tc(const float* __restrict__ Aext, int use_ext,
                                                 const float* __restrict__ B, int K) {
    const float* A = use_ext ? Aext : (const float*)g_a;
    __shared__ uint32_t As[2][128][20];   // [buf][m][k]
    __shared__ uint32_t Bs[2][16][136];   // [buf][k][n]

    int bm = blockIdx.y * 128, bn = blockIdx.x * 128;
    int tid = threadIdx.x;
    int wid = tid >> 5, lane = tid & 31;
    int wr = wid >> 1, wc = wid & 1;
    int gid = lane >> 2, tig = lane & 3;

    int a_row0 = tid >> 2, a_kq0 = (tid & 3) << 2;
    int a_row1 = (tid + 256) >> 2, a_kq1 = ((tid + 256) & 3) << 2;
    int b_kk0 = tid >> 5, b_n40 = (tid & 31) << 2;
    int b_kk1 = (tid + 256) >> 5, b_n41 = ((tid + 256) & 31) << 2;

    float acc[2][8][4];
    #pragma unroll
    for (int i = 0; i < 2; i++)
        #pragma unroll
        for (int j = 0; j < 8; j++)
            #pragma unroll
            for (int l = 0; l < 4; l++) acc[i][j][l] = 0.f;

    int T = (K + 15) / 16;

    auto load_tile = [&](int tile, int buf) {
        int k0 = tile * 16;
        {
            int grow = bm + a_row0;
            int rem = K - (k0 + a_kq0);
            int bytes = (grow < NN && rem > 0) ? (rem >= 4 ? 16 : rem * 4) : 0;
            const float* src = (bytes > 0) ? (A + (size_t)grow * K + k0 + a_kq0) : A;
            cp16((uint32_t)__cvta_generic_to_shared(&As[buf][a_row0][a_kq0]), src, bytes);
        }
        {
            int grow = bm + a_row1;
            int rem = K - (k0 + a_kq1);
            int bytes = (grow < NN && rem > 0) ? (rem >= 4 ? 16 : rem * 4) : 0;
            const float* src = (bytes > 0) ? (A + (size_t)grow * K + k0 + a_kq1) : A;
            cp16((uint32_t)__cvta_generic_to_shared(&As[buf][a_row1][a_kq1]), src, bytes);
        }
        {
            int gk = k0 + b_kk0;
            int bytes = (gk < K) ? 16 : 0;
            const float* src = (bytes > 0) ? (B + (size_t)gk * 256 + bn + b_n40) : B;
            cp16((uint32_t)__cvta_generic_to_shared(&Bs[buf][b_kk0][b_n40]), src, bytes);
        }
        {
            int gk = k0 + b_kk1;
            int bytes = (gk < K) ? 16 : 0;
            const float* src = (bytes > 0) ? (B + (size_t)gk * 256 + bn + b_n41) : B;
            cp16((uint32_t)__cvta_generic_to_shared(&Bs[buf][b_kk1][b_n41]), src, bytes);
        }
    };

    load_tile(0, 0);
    cp_commit();

    for (int it = 0; it < T; it++) {
        if (it + 1 < T) load_tile(it + 1, (it + 1) & 1);
        cp_commit();
        cp_wait1();
        __syncthreads();

        int buf = it & 1;
        #pragma unroll
        for (int ks = 0; ks < 16; ks += 8) {
            uint32_t a[2][4], b[8][2];
            #pragma unroll
            for (int mt = 0; mt < 2; mt++) {
                int r = wr * 32 + mt * 16;
                a[mt][0] = As[buf][r + gid][ks + tig];
                a[mt][1] = As[buf][r + gid + 8][ks + tig];
                a[mt][2] = As[buf][r + gid][ks + tig + 4];
                a[mt][3] = As[buf][r + gid + 8][ks + tig + 4];
            }
            #pragma unroll
            for (int nt = 0; nt < 8; nt++) {
                int c = wc * 64 + nt * 8 + gid;
                b[nt][0] = Bs[buf][ks + tig][c];
                b[nt][1] = Bs[buf][ks + tig + 4][c];
            }
            #pragma unroll
            for (int mt = 0; mt < 2; mt++)
                #pragma unroll
                for (int nt = 0; nt < 8; nt++) {
                    asm volatile(
                        "mma.sync.aligned.m16n8k8.row.col.f32.tf32.tf32.f32 "
                        "{%0,%1,%2,%3}, {%4,%5,%6,%7}, {%8,%9}, {%0,%1,%2,%3};"
                        : "+f"(acc[mt][nt][0]), "+f"(acc[mt][nt][1]),
                          "+f"(acc[mt][nt][2]), "+f"(acc[mt][nt][3])
                        : "r"(a[mt][0]), "r"(a[mt][1]), "r"(a[mt][2]), "r"(a[mt][3]),
                          "r"(b[nt][0]), "r"(b[nt][1]));
                }
        }
        __syncthreads();
    }

    #pragma unroll
    for (int mt = 0; mt < 2; mt++) {
        #pragma unroll
        for (int nt = 0; nt < 8; nt++) {
            int r0 = bm + wr * 32 + mt * 16 + gid;
            int cc = bn + wc * 64 + nt * 8 + tig * 2;
            if (r0 < NN) {
                float2 v; v.x = acc[mt][nt][0]; v.y = acc[mt][nt][1];
                *(float2*)(g_t + (size_t)r0 * 256 + cc) = v;
            }
            if (r0 + 8 < NN) {
                float2 v; v.x = acc[mt][nt][2]; v.y = acc[mt][nt][3];
                *(float2*)(g_t + (size_t)(r0 + 8) * 256 + cc) = v;
            }
        }
    }
}

// ---------------- aggregation: 1 warp/node, edge unroll x4 (8 gathers in flight) ----------------
__global__ void k_agg(const float* __restrict__ bias, int relu) {
    int gw = (blockIdx.x * blockDim.x + threadIdx.x) >> 5;
    int lane = threadIdx.x & 31;
    if (gw >= NN) return;
    int n = gw;
    float dn = g_dinv[n];
    float sw = dn * dn;
    const float4* trow = (const float4*)(g_t + (size_t)n * 256);
    float4 a0 = __ldg(&trow[lane]), a1 = __ldg(&trow[lane + 32]);
    a0.x *= sw; a0.y *= sw; a0.z *= sw; a0.w *= sw;
    a1.x *= sw; a1.y *= sw; a1.z *= sw; a1.w *= sw;

    int beg = g_rowptr[n], end = g_rowptr[n + 1];
    const float4* t4 = (const float4*)g_t;
    int i = beg;
    for (; i + 4 <= end; i += 4) {
        int s0 = g_csr_src[i],   s1 = g_csr_src[i+1];
        int s2 = g_csr_src[i+2], s3 = g_csr_src[i+3];
        float w0 = g_csr_w[i],   w1 = g_csr_w[i+1];
        float w2 = g_csr_w[i+2], w3 = g_csr_w[i+3];
        float4 p0 = __ldg(&t4[(size_t)s0 * 64 + lane]);
        float4 q0 = __ldg(&t4[(size_t)s0 * 64 + lane + 32]);
        float4 p1 = __ldg(&t4[(size_t)s1 * 64 + lane]);
        float4 q1 = __ldg(&t4[(size_t)s1 * 64 + lane + 32]);
        float4 p2 = __ldg(&t4[(size_t)s2 * 64 + lane]);
        float4 q2 = __ldg(&t4[(size_t)s2 * 64 + lane + 32]);
        float4 p3 = __ldg(&t4[(size_t)s3 * 64 + lane]);
        float4 q3 = __ldg(&t4[(size_t)s3 * 64 + lane + 32]);
        a0.x += w0*p0.x + w1*p1.x + w2*p2.x + w3*p3.x;
        a0.y += w0*p0.y + w1*p1.y + w2*p2.y + w3*p3.y;
        a0.z += w0*p0.z + w1*p1.z + w2*p2.z + w3*p3.z;
        a0.w += w0*p0.w + w1*p1.w + w2*p2.w + w3*p3.w;
        a1.x += w0*q0.x + w1*q1.x + w2*q2.x + w3*q3.x;
        a1.y += w0*q0.y + w1*q1.y + w2*q2.y + w3*q3.y;
        a1.z += w0*q0.z + w1*q1.z + w2*q2.z + w3*q3.z;
        a1.w += w0*q0.w + w1*q1.w + w2*q2.w + w3*q3.w;
    }
    for (; i < end; i++) {
        int s = g_csr_src[i];
        float w = g_csr_w[i];
        float4 v0 = __ldg(&t4[(size_t)s * 64 + lane]);
        float4 v1 = __ldg(&t4[(size_t)s * 64 + lane + 32]);
        a0.x += w * v0.x; a0.y += w * v0.y; a0.z += w * v0.z; a0.w += w * v0.w;
        a1.x += w * v1.x; a1.y += w * v1.y; a1.z += w * v1.z; a1.w += w * v1.w;
    }

    float4 b0 = ((const float4*)bias)[lane];
    float4 b1 = ((const float4*)bias)[lane + 32];
    a0.x += b0.x; a0.y += b0.y; a0.z += b0.z; a0.w += b0.w;
    a1.x += b1.x; a1.y += b1.y; a1.z += b1.z; a1.w += b1.w;
    if (relu) {
        a0.x = fmaxf(a0.x, 0.f); a0.y = fmaxf(a0.y, 0.f);
        a0.z = fmaxf(a0.z, 0.f); a0.w = fmaxf(a0.w, 0.f);
        a1.x = fmaxf(a1.x, 0.f); a1.y = fmaxf(a1.y, 0.f);
        a1.z = fmaxf(a1.z, 0.f); a1.w = fmaxf(a1.w, 0.f);
    }
    float4* orow = (float4*)(g_a + (size_t)n * 256);
    orow[lane] = a0; orow[lane + 32] = a1;
}

// ---------------- fused mean-pool + classifier: one block per graph ----------------
__global__ void k_head(const int* __restrict__ batch,
                       const float* __restrict__ Wc1, const float* __restrict__ bc1,
                       const float* __restrict__ Wc2, const float* __restrict__ bc2,
                       const float* __restrict__ Wc3, const float* __restrict__ bc3,
                       float* __restrict__ out) {
    int g = blockIdx.x, t = threadIdx.x;
    __shared__ float p[256], q1[16], q2[64];
    __shared__ int slo, shi;
    if (t == 0) {
        int l = 0, r = NN;
        while (l < r) { int m = (l + r) >> 1; if (batch[m] < g) l = m + 1; else r = m; }
        slo = l;
        l = 0; r = NN;
        while (l < r) { int m = (l + r) >> 1; if (batch[m] < g + 1) l = m + 1; else r = m; }
        shi = l;
    }
    __syncthreads();
    int lo = slo, hi = shi;
    float s = 0.f;
    for (int n = lo; n < hi; n++) s += g_a[(size_t)n * 256 + t];
    int cnt = hi - lo;
    float inv = (cnt > 0) ? (1.0f / (float)cnt) : 1.0f;
    p[t] = s * inv;
    __syncthreads();

    float* o1 = out;
    float* o2 = out + 256 * 16;
    float* o3 = out + 256 * 16 + 256 * 64;

    if (t < 16) {
        float v = bc1[t];
        for (int k = 0; k < 256; k++) v += p[k] * Wc1[k * 16 + t];
        q1[t] = v;
        o1[g * 16 + t] = v;
    }
    __syncthreads();
    if (t == 0) {
        float m = q1[0];
        for (int i = 1; i < 16; i++) m = fmaxf(m, q1[i]);
        float sum = 0.f;
        for (int i = 0; i < 16; i++) { q1[i] = expf(q1[i] - m); sum += q1[i]; }
        float inv2 = 1.f / sum;
        for (int i = 0; i < 16; i++) q1[i] *= inv2;
    }
    __syncthreads();
    if (t < 64) {
        float v = bc2[t];
        for (int k = 0; k < 256; k++) v += p[k] * Wc2[k * 64 + t];
        for (int k = 0; k < 16; k++) v += q1[k] * Wc2[(256 + k) * 64 + t];
        q2[t] = v;
        o2[g * 64 + t] = v;
    }
    __syncthreads();
    if (t == 0) {
        float m = q2[0];
        for (int i = 1; i < 64; i++) m = fmaxf(m, q2[i]);
        float sum = 0.f;
        for (int i = 0; i < 64; i++) { q2[i] = expf(q2[i] - m); sum += q2[i]; }
        float inv2 = 1.f / sum;
        for (int i = 0; i < 64; i++) q2[i] *= inv2;
    }
    __syncthreads();
    {
        float v = bc3[t];
        for (int k = 0; k < 256; k++) v += p[k] * Wc3[k * 256 + t];
        for (int k = 0; k < 64; k++) v += q2[k] * Wc3[(256 + k) * 256 + t];
        o3[g * 256 + t] = v;
    }
}

// ---------------- launch ----------------
extern "C" void kernel_launch(void* const* d_in, const int* in_sizes, int n_in,
                              void* d_out, int out_size) {
    const float* x     = (const float*)d_in[0];
    const int*   ei    = (const int*)d_in[1];
    const int*   batch = (const int*)d_in[2];
    const float* W1 = (const float*)d_in[3],  *b1 = (const float*)d_in[4];
    const float* W2 = (const float*)d_in[5],  *b2 = (const float*)d_in[6];
    const float* W3 = (const float*)d_in[7],  *b3 = (const float*)d_in[8];
    const float* Wc1 = (const float*)d_in[9],  *bc1 = (const float*)d_in[10];
    const float* Wc2 = (const float*)d_in[11], *bc2 = (const float*)d_in[12];
    const float* Wc3 = (const float*)d_in[13], *bc3 = (const float*)d_in[14];
    float* out = (float*)d_out;

    k_zero<<<(NN + 255) / 256, 256>>>();
    k_hist<<<NE / 256, 256>>>(ei);
    k_scan<<<1, 1024>>>();
    k_build<<<NE / 256, 256>>>(ei);

    dim3 gg(2, (NN + 127) / 128);  // (2, 391)
    int agg_blocks = (NN * 32 + 255) / 256;  // 1 warp per node
    k_gemm_tc<<<gg, 256>>>(x, 1, W1, INDIM);
    k_agg<<<agg_blocks, 256>>>(b1, 1);
    k_gemm_tc<<<gg, 256>>>(nullptr, 0, W2, HID);
    k_agg<<<agg_blocks, 256>>>(b2, 1);
    k_gemm_tc<<<gg, 256>>>(nullptr, 0, W3, HID);
    k_agg<<<agg_blocks, 256>>>(b3, 0);

    k_head<<<NG, 256>>>(batch, Wc1, bc1, Wc2, bc2, Wc3, bc3, out);
}

// round 8
// speedup vs baseline: 1.1256x; 1.0941x over previous
#include <cuda_runtime.h>
#include <cuda_fp16.h>
#include <stdint.h>

#define NN 50000
#define NE 800000
#define NG 256
#define INDIM 300
#define HID 256

// ---------------- scratch (device globals; no allocation allowed) ----------------
__device__ __align__(16) __half g_t16[(size_t)NN * HID];  // transformed (h @ W), fp16
__device__ __align__(16) float g_a[(size_t)NN * HID];     // aggregated output, fp32
__device__ float g_dinv[NN];
__device__ int   g_cnt[NN];
__device__ int   g_rowptr[NN + 1];
__device__ int   g_cursor[NN];
__device__ int   g_csr_src[NE];
__device__ float g_csr_w[NE];

// ---------------- graph preprocessing ----------------
__global__ void k_zero() {
    int i = blockIdx.x * blockDim.x + threadIdx.x;
    if (i < NN) g_cnt[i] = 0;
}

__global__ void k_hist(const int* __restrict__ ei) {
    int e = blockIdx.x * blockDim.x + threadIdx.x;
    if (e < NE) {
        int d = ei[NE + e];
        if (d >= 0 && d < NN) atomicAdd(&g_cnt[d], 1);
    }
}

// single-block: exclusive scan cnt->rowptr, plus dinv + cursor init
__global__ void k_scan() {
    const int CH = (NN + 1023) / 1024;  // 49
    __shared__ int part[1024];
    int t = threadIdx.x;
    int begin = t * CH;
    int end = begin + CH; if (end > NN) end = NN; if (begin > NN) begin = NN;
    int s = 0;
    for (int i = begin; i < end; i++) s += g_cnt[i];
    part[t] = s;
    __syncthreads();
    if (t == 0) {
        int run = 0;
        for (int i = 0; i < 1024; i++) { int v = part[i]; part[i] = run; run += v; }
    }
    __syncthreads();
    int run = part[t];
    for (int i = begin; i < end; i++) {
        int c = g_cnt[i];
        g_rowptr[i] = run; run += c;
        g_dinv[i] = rsqrtf((float)(c + 1));
        g_cursor[i] = 0;
    }
    if (t == 1023) g_rowptr[NN] = run;
}

__global__ void k_build(const int* __restrict__ ei) {
    int e = blockIdx.x * blockDim.x + threadIdx.x;
    if (e >= NE) return;
    int s = ei[e];
    int d = ei[NE + e];
    if (s < 0 || s >= NN || d < 0 || d >= NN) return;
    int pos = g_rowptr[d] + atomicAdd(&g_cursor[d], 1);
    g_csr_src[pos] = s;
    g_csr_w[pos] = g_dinv[s] * g_dinv[d];
}

// ---------------- tf32 tensor-core GEMM, 2-stage cp.async pipeline ----------------
__device__ __forceinline__ void cp16(uint32_t dst, const void* src, int srcbytes) {
    asm volatile("cp.async.cg.shared.global [%0], [%1], 16, %2;\n"
                 :: "r"(dst), "l"(src), "r"(srcbytes));
}
__device__ __forceinline__ void cp_commit() {
    asm volatile("cp.async.commit_group;\n");
}
__device__ __forceinline__ void cp_wait1() {
    asm volatile("cp.async.wait_group 1;\n");
}

// block tile 128x128, BK=16, 256 threads = 8 warps (4x2), warp tile 32x64
// output stored as fp16 into g_t16
__global__ void __launch_bounds__(256) k_gemm_tc(const float* __restrict__ Aext, int use_ext,
                                                 const float* __restrict__ B, int K) {
    const float* A = use_ext ? Aext : (const float*)g_a;
    __shared__ uint32_t As[2][128][20];   // [buf][m][k]
    __shared__ uint32_t Bs[2][16][136];   // [buf][k][n]

    int bm = blockIdx.y * 128, bn = blockIdx.x * 128;
    int tid = threadIdx.x;
    int wid = tid >> 5, lane = tid & 31;
    int wr = wid >> 1, wc = wid & 1;
    int gid = lane >> 2, tig = lane & 3;

    int a_row0 = tid >> 2, a_kq0 = (tid & 3) << 2;
    int a_row1 = (tid + 256) >> 2, a_kq1 = ((tid + 256) & 3) << 2;
    int b_kk0 = tid >> 5, b_n40 = (tid & 31) << 2;
    int b_kk1 = (tid + 256) >> 5, b_n41 = ((tid + 256) & 31) << 2;

    float acc[2][8][4];
    #pragma unroll
    for (int i = 0; i < 2; i++)
        #pragma unroll
        for (int j = 0; j < 8; j++)
            #pragma unroll
            for (int l = 0; l < 4; l++) acc[i][j][l] = 0.f;

    int T = (K + 15) / 16;

    auto load_tile = [&](int tile, int buf) {
        int k0 = tile * 16;
        {
            int grow = bm + a_row0;
            int rem = K - (k0 + a_kq0);
            int bytes = (grow < NN && rem > 0) ? (rem >= 4 ? 16 : rem * 4) : 0;
            const float* src = (bytes > 0) ? (A + (size_t)grow * K + k0 + a_kq0) : A;
            cp16((uint32_t)__cvta_generic_to_shared(&As[buf][a_row0][a_kq0]), src, bytes);
        }
        {
            int grow = bm + a_row1;
            int rem = K - (k0 + a_kq1);
            int bytes = (grow < NN && rem > 0) ? (rem >= 4 ? 16 : rem * 4) : 0;
            const float* src = (bytes > 0) ? (A + (size_t)grow * K + k0 + a_kq1) : A;
            cp16((uint32_t)__cvta_generic_to_shared(&As[buf][a_row1][a_kq1]), src, bytes);
        }
        {
            int gk = k0 + b_kk0;
            int bytes = (gk < K) ? 16 : 0;
            const float* src = (bytes > 0) ? (B + (size_t)gk * 256 + bn + b_n40) : B;
            cp16((uint32_t)__cvta_generic_to_shared(&Bs[buf][b_kk0][b_n40]), src, bytes);
        }
        {
            int gk = k0 + b_kk1;
            int bytes = (gk < K) ? 16 : 0;
            const float* src = (bytes > 0) ? (B + (size_t)gk * 256 + bn + b_n41) : B;
            cp16((uint32_t)__cvta_generic_to_shared(&Bs[buf][b_kk1][b_n41]), src, bytes);
        }
    };

    load_tile(0, 0);
    cp_commit();

    for (int it = 0; it < T; it++) {
        if (it + 1 < T) load_tile(it + 1, (it + 1) & 1);
        cp_commit();
        cp_wait1();
        __syncthreads();

        int buf = it & 1;
        #pragma unroll
        for (int ks = 0; ks < 16; ks += 8) {
            uint32_t a[2][4], b[8][2];
            #pragma unroll
            for (int mt = 0; mt < 2; mt++) {
                int r = wr * 32 + mt * 16;
                a[mt][0] = As[buf][r + gid][ks + tig];
                a[mt][1] = As[buf][r + gid + 8][ks + tig];
                a[mt][2] = As[buf][r + gid][ks + tig + 4];
                a[mt][3] = As[buf][r + gid + 8][ks + tig + 4];
            }
            #pragma unroll
            for (int nt = 0; nt < 8; nt++) {
                int c = wc * 64 + nt * 8 + gid;
                b[nt][0] = Bs[buf][ks + tig][c];
                b[nt][1] = Bs[buf][ks + tig + 4][c];
            }
            #pragma unroll
            for (int mt = 0; mt < 2; mt++)
                #pragma unroll
                for (int nt = 0; nt < 8; nt++) {
                    asm volatile(
                        "mma.sync.aligned.m16n8k8.row.col.f32.tf32.tf32.f32 "
                        "{%0,%1,%2,%3}, {%4,%5,%6,%7}, {%8,%9}, {%0,%1,%2,%3};"
                        : "+f"(acc[mt][nt][0]), "+f"(acc[mt][nt][1]),
                          "+f"(acc[mt][nt][2]), "+f"(acc[mt][nt][3])
                        : "r"(a[mt][0]), "r"(a[mt][1]), "r"(a[mt][2]), "r"(a[mt][3]),
                          "r"(b[nt][0]), "r"(b[nt][1]));
                }
        }
        __syncthreads();
    }

    // ---- store as fp16 (half2 per acc pair) ----
    #pragma unroll
    for (int mt = 0; mt < 2; mt++) {
        #pragma unroll
        for (int nt = 0; nt < 8; nt++) {
            int r0 = bm + wr * 32 + mt * 16 + gid;
            int cc = bn + wc * 64 + nt * 8 + tig * 2;   // even
            if (r0 < NN) {
                __half2 h = __floats2half2_rn(acc[mt][nt][0], acc[mt][nt][1]);
                *(__half2*)(g_t16 + (size_t)r0 * 256 + cc) = h;
            }
            if (r0 + 8 < NN) {
                __half2 h = __floats2half2_rn(acc[mt][nt][2], acc[mt][nt][3]);
                *(__half2*)(g_t16 + (size_t)(r0 + 8) * 256 + cc) = h;
            }
        }
    }
}

// ---------------- aggregation: 1 warp/node, fp16 gather (512B/edge), unroll x4 ----------------
__device__ __forceinline__ void acc8(float* a, uint4 v, float w) {
    __half2* h = (__half2*)&v;
    #pragma unroll
    for (int j = 0; j < 4; j++) {
        float2 f = __half22float2(h[j]);
        a[2 * j + 0] += w * f.x;
        a[2 * j + 1] += w * f.y;
    }
}

__global__ void k_agg(const float* __restrict__ bias, int relu) {
    int gw = (blockIdx.x * blockDim.x + threadIdx.x) >> 5;
    int lane = threadIdx.x & 31;
    if (gw >= NN) return;
    int n = gw;
    const uint4* t4 = (const uint4*)g_t16;   // row = 32 uint4 (256 halves)

    float dn = g_dinv[n];
    float sw = dn * dn;
    float a[8] = {};
    acc8(a, __ldg(&t4[(size_t)n * 32 + lane]), sw);   // self term

    int beg = g_rowptr[n], end = g_rowptr[n + 1];
    int i = beg;
    for (; i + 4 <= end; i += 4) {
        int s0 = g_csr_src[i],   s1 = g_csr_src[i+1];
        int s2 = g_csr_src[i+2], s3 = g_csr_src[i+3];
        float w0 = g_csr_w[i],   w1 = g_csr_w[i+1];
        float w2 = g_csr_w[i+2], w3 = g_csr_w[i+3];
        uint4 v0 = __ldg(&t4[(size_t)s0 * 32 + lane]);
        uint4 v1 = __ldg(&t4[(size_t)s1 * 32 + lane]);
        uint4 v2 = __ldg(&t4[(size_t)s2 * 32 + lane]);
        uint4 v3 = __ldg(&t4[(size_t)s3 * 32 + lane]);
        acc8(a, v0, w0); acc8(a, v1, w1); acc8(a, v2, w2); acc8(a, v3, w3);
    }
    for (; i < end; i++) {
        int s = g_csr_src[i];
        float w = g_csr_w[i];
        acc8(a, __ldg(&t4[(size_t)s * 32 + lane]), w);
    }

    // bias over this lane's 8 columns [lane*8, lane*8+8)
    float4 b0 = ((const float4*)bias)[lane * 2];
    float4 b1 = ((const float4*)bias)[lane * 2 + 1];
    a[0] += b0.x; a[1] += b0.y; a[2] += b0.z; a[3] += b0.w;
    a[4] += b1.x; a[5] += b1.y; a[6] += b1.z; a[7] += b1.w;
    if (relu) {
        #pragma unroll
        for (int j = 0; j < 8; j++) a[j] = fmaxf(a[j], 0.f);
    }
    float4* orow = (float4*)(g_a + (size_t)n * 256);
    orow[lane * 2]     = make_float4(a[0], a[1], a[2], a[3]);
    orow[lane * 2 + 1] = make_float4(a[4], a[5], a[6], a[7]);
}

// ---------------- fused mean-pool + classifier: one block per graph ----------------
__global__ void k_head(const int* __restrict__ batch,
                       const float* __restrict__ Wc1, const float* __restrict__ bc1,
                       const float* __restrict__ Wc2, const float* __restrict__ bc2,
                       const float* __restrict__ Wc3, const float* __restrict__ bc3,
                       float* __restrict__ out) {
    int g = blockIdx.x, t = threadIdx.x;
    __shared__ float p[256], q1[16], q2[64];
    __shared__ int slo, shi;
    if (t == 0) {
        int l = 0, r = NN;
        while (l < r) { int m = (l + r) >> 1; if (batch[m] < g) l = m + 1; else r = m; }
        slo = l;
        l = 0; r = NN;
        while (l < r) { int m = (l + r) >> 1; if (batch[m] < g + 1) l = m + 1; else r = m; }
        shi = l;
    }
    __syncthreads();
    int lo = slo, hi = shi;
    float s = 0.f;
    for (int n = lo; n < hi; n++) s += g_a[(size_t)n * 256 + t];
    int cnt = hi - lo;
    float inv = (cnt > 0) ? (1.0f / (float)cnt) : 1.0f;
    p[t] = s * inv;
    __syncthreads();

    float* o1 = out;
    float* o2 = out + 256 * 16;
    float* o3 = out + 256 * 16 + 256 * 64;

    if (t < 16) {
        float v = bc1[t];
        for (int k = 0; k < 256; k++) v += p[k] * Wc1[k * 16 + t];
        q1[t] = v;
        o1[g * 16 + t] = v;
    }
    __syncthreads();
    if (t == 0) {
        float m = q1[0];
        for (int i = 1; i < 16; i++) m = fmaxf(m, q1[i]);
        float sum = 0.f;
        for (int i = 0; i < 16; i++) { q1[i] = expf(q1[i] - m); sum += q1[i]; }
        float inv2 = 1.f / sum;
        for (int i = 0; i < 16; i++) q1[i] *= inv2;
    }
    __syncthreads();
    if (t < 64) {
        float v = bc2[t];
        for (int k = 0; k < 256; k++) v += p[k] * Wc2[k * 64 + t];
        for (int k = 0; k < 16; k++) v += q1[k] * Wc2[(256 + k) * 64 + t];
        q2[t] = v;
        o2[g * 64 + t] = v;
    }
    __syncthreads();
    if (t == 0) {
        float m = q2[0];
        for (int i = 1; i < 64; i++) m = fmaxf(m, q2[i]);
        float sum = 0.f;
        for (int i = 0; i < 64; i++) { q2[i] = expf(q2[i] - m); sum += q2[i]; }
        float inv2 = 1.f / sum;
        for (int i = 0; i < 64; i++) q2[i] *= inv2;
    }
    __syncthreads();
    {
        float v = bc3[t];
        for (int k = 0; k < 256; k++) v += p[k] * Wc3[k * 256 + t];
        for (int k = 0; k < 64; k++) v += q2[k] * Wc3[(256 + k) * 256 + t];
        o3[g * 256 + t] = v;
    }
}

// ---------------- launch ----------------
extern "C" void kernel_launch(void* const* d_in, const int* in_sizes, int n_in,
                              void* d_out, int out_size) {
    const float* x     = (const float*)d_in[0];
    const int*   ei    = (const int*)d_in[1];
    const int*   batch = (const int*)d_in[2];
    const float* W1 = (const float*)d_in[3],  *b1 = (const float*)d_in[4];
    const float* W2 = (const float*)d_in[5],  *b2 = (const float*)d_in[6];
    const float* W3 = (const float*)d_in[7],  *b3 = (const float*)d_in[8];
    const float* Wc1 = (const float*)d_in[9],  *bc1 = (const float*)d_in[10];
    const float* Wc2 = (const float*)d_in[11], *bc2 = (const float*)d_in[12];
    const float* Wc3 = (const float*)d_in[13], *bc3 = (const float*)d_in[14];
    float* out = (float*)d_out;

    k_zero<<<(NN + 255) / 256, 256>>>();
    k_hist<<<NE / 256, 256>>>(ei);
    k_scan<<<1, 1024>>>();
    k_build<<<NE / 256, 256>>>(ei);

    dim3 gg(2, (NN + 127) / 128);  // (2, 391)
    int agg_blocks = (NN * 32 + 255) / 256;  // 1 warp per node
    k_gemm_tc<<<gg, 256>>>(x, 1, W1, INDIM);
    k_agg<<<agg_blocks, 256>>>(b1, 1);
    k_gemm_tc<<<gg, 256>>>(nullptr, 0, W2, HID);
    k_agg<<<agg_blocks, 256>>>(b2, 1);
    k_gemm_tc<<<gg, 256>>>(nullptr, 0, W3, HID);
    k_agg<<<agg_blocks, 256>>>(b3, 0);

    k_head<<<NG, 256>>>(batch, Wc1, bc1, Wc2, bc2, Wc3, bc3, out);
}

// round 10
// speedup vs baseline: 1.2171x; 1.0813x over previous
#include <cuda_runtime.h>
#include <cuda_fp16.h>
#include <stdint.h>

#define NN 50000
#define NE 800000
#define NG 256
#define INDIM 300
#define KP1 320          // x padded K (multiple of 32)
#define HID 256

// ---------------- scratch (device globals; no allocation allowed) ----------------
__device__ __align__(16) __half   g_x16[(size_t)NN * KP1];   // x in fp16, K padded
__device__ __align__(16) __half   g_t16[(size_t)NN * HID];   // transformed (h @ W), fp16
__device__ __align__(16) __half   g_a16[(size_t)NN * HID];   // aggregated output, fp16
__device__ __align__(16) uint32_t g_w1p[(KP1/2) * HID];      // W1 packed k-pairs (fp16x2)
__device__ __align__(16) uint32_t g_w2p[(HID/2) * HID];
__device__ __align__(16) uint32_t g_w3p[(HID/2) * HID];
__device__ float g_dinv[NN];
__device__ int   g_cnt[NN];
__device__ int   g_rowptr[NN + 1];
__device__ int   g_cursor[NN];
__device__ int   g_csr_src[NE];
__device__ float g_csr_w[NE];

// ---------------- graph preprocessing ----------------
__global__ void k_zero() {
    int i = blockIdx.x * blockDim.x + threadIdx.x;
    if (i < NN) g_cnt[i] = 0;
}

__global__ void k_hist(const int* __restrict__ ei) {
    int e = blockIdx.x * blockDim.x + threadIdx.x;
    if (e < NE) {
        int d = ei[NE + e];
        if (d >= 0 && d < NN) atomicAdd(&g_cnt[d], 1);
    }
}

__global__ void k_scan() {
    const int CH = (NN + 1023) / 1024;  // 49
    __shared__ int part[1024];
    int t = threadIdx.x;
    int begin = t * CH;
    int end = begin + CH; if (end > NN) end = NN; if (begin > NN) begin = NN;
    int s = 0;
    for (int i = begin; i < end; i++) s += g_cnt[i];
    part[t] = s;
    __syncthreads();
    if (t == 0) {
        int run = 0;
        for (int i = 0; i < 1024; i++) { int v = part[i]; part[i] = run; run += v; }
    }
    __syncthreads();
    int run = part[t];
    for (int i = begin; i < end; i++) {
        int c = g_cnt[i];
        g_rowptr[i] = run; run += c;
        g_dinv[i] = rsqrtf((float)(c + 1));
        g_cursor[i] = 0;
    }
    if (t == 1023) g_rowptr[NN] = run;
}

__global__ void k_build(const int* __restrict__ ei) {
    int e = blockIdx.x * blockDim.x + threadIdx.x;
    if (e >= NE) return;
    int s = ei[e];
    int d = ei[NE + e];
    if (s < 0 || s >= NN || d < 0 || d >= NN) return;
    int pos = g_rowptr[d] + atomicAdd(&g_cursor[d], 1);
    g_csr_src[pos] = s;
    g_csr_w[pos] = g_dinv[s] * g_dinv[d];
}

// ---------------- input conversions (device symbols referenced IN device code) ----------------
__global__ void k_cvt_x(const float* __restrict__ x) {
    size_t i = (size_t)blockIdx.x * blockDim.x + threadIdx.x;
    if (i >= (size_t)NN * KP1) return;
    int col = (int)(i % KP1);
    int row = (int)(i / KP1);
    float v = (col < INDIM) ? x[(size_t)row * INDIM + col] : 0.f;
    g_x16[i] = __float2half_rn(v);
}

// pack W[K][256] fp32 -> out[k2][n] = (half(W[2k2][n]), half(W[2k2+1][n]))
// which: 0 -> g_w1p, 1 -> g_w2p, 2 -> g_w3p
__global__ void k_cvt_w(const float* __restrict__ W, int which, int K, int K2) {
    int i = blockIdx.x * blockDim.x + threadIdx.x;
    if (i >= K2 * HID) return;
    int n = i % HID, k2 = i / HID;
    int ka = 2 * k2, kb = 2 * k2 + 1;
    float lo = (ka < K) ? W[(size_t)ka * HID + n] : 0.f;
    float hi = (kb < K) ? W[(size_t)kb * HID + n] : 0.f;
    __half2 h = __floats2half2_rn(lo, hi);
    uint32_t* out = (which == 0) ? g_w1p : (which == 1) ? g_w2p : g_w3p;
    out[i] = *(uint32_t*)&h;
}

// ---------------- fp16 tensor-core GEMM, 2-stage cp.async pipeline ----------------
// layer: 0 -> A=g_x16 (K=KP1), W=g_w1p ; 1 -> A=g_a16, W=g_w2p ; 2 -> A=g_a16, W=g_w3p
__device__ __forceinline__ void cp16(uint32_t dst, const void* src, int srcbytes) {
    asm volatile("cp.async.cg.shared.global [%0], [%1], 16, %2;\n"
                 :: "r"(dst), "l"(src), "r"(srcbytes));
}
__device__ __forceinline__ void cp_commit() {
    asm volatile("cp.async.commit_group;\n");
}
__device__ __forceinline__ void cp_wait1() {
    asm volatile("cp.async.wait_group 1;\n");
}

__global__ void __launch_bounds__(256) k_gemm_f16(int layer) {
    const __half* A = (layer == 0) ? g_x16 : g_a16;
    const uint32_t* Bpk = (layer == 0) ? g_w1p : (layer == 1) ? g_w2p : g_w3p;
    const int K = (layer == 0) ? KP1 : HID;

    __shared__ __align__(16) __half   As[2][128][40];    // [buf][m][k], pad 40
    __shared__ __align__(16) uint32_t Bs[2][16][136];    // [buf][k2][n], pad 136

    int bm = blockIdx.y * 128, bn = blockIdx.x * 128;
    int tid = threadIdx.x;
    int wid = tid >> 5, lane = tid & 31;
    int wr = wid >> 1, wc = wid & 1;
    int gid = lane >> 2, tig = lane & 3;

    int a_row0 = tid >> 2, a_k80 = (tid & 3) << 3;
    int a_row1 = (tid + 256) >> 2, a_k81 = ((tid + 256) & 3) << 3;
    int b_k20 = tid >> 5, b_n40 = (tid & 31) << 2;
    int b_k21 = (tid + 256) >> 5, b_n41 = ((tid + 256) & 31) << 2;

    float acc[2][8][4];
    #pragma unroll
    for (int i = 0; i < 2; i++)
        #pragma unroll
        for (int j = 0; j < 8; j++)
            #pragma unroll
            for (int l = 0; l < 4; l++) acc[i][j][l] = 0.f;

    int T = K >> 5;   // K multiple of 32

    auto load_tile = [&](int tile, int buf) {
        int k0 = tile << 5;
        {
            int grow = bm + a_row0;
            int bytes = (grow < NN) ? 16 : 0;
            const __half* src = (bytes > 0) ? (A + (size_t)grow * K + k0 + a_k80) : A;
            cp16((uint32_t)__cvta_generic_to_shared(&As[buf][a_row0][a_k80]), src, bytes);
        }
        {
            int grow = bm + a_row1;
            int bytes = (grow < NN) ? 16 : 0;
            const __half* src = (bytes > 0) ? (A + (size_t)grow * K + k0 + a_k81) : A;
            cp16((uint32_t)__cvta_generic_to_shared(&As[buf][a_row1][a_k81]), src, bytes);
        }
        int k20 = k0 >> 1;
        cp16((uint32_t)__cvta_generic_to_shared(&Bs[buf][b_k20][b_n40]),
             Bpk + (size_t)(k20 + b_k20) * 256 + bn + b_n40, 16);
        cp16((uint32_t)__cvta_generic_to_shared(&Bs[buf][b_k21][b_n41]),
             Bpk + (size_t)(k20 + b_k21) * 256 + bn + b_n41, 16);
    };

    load_tile(0, 0);
    cp_commit();

    for (int it = 0; it < T; it++) {
        if (it + 1 < T) load_tile(it + 1, (it + 1) & 1);
        cp_commit();
        cp_wait1();
        __syncthreads();

        int buf = it & 1;
        #pragma unroll
        for (int ks = 0; ks < 32; ks += 16) {
            uint32_t a[2][4], b[8][2];
            #pragma unroll
            for (int mt = 0; mt < 2; mt++) {
                int r = wr * 32 + mt * 16;
                a[mt][0] = *(const uint32_t*)&As[buf][r + gid][ks + 2 * tig];
                a[mt][1] = *(const uint32_t*)&As[buf][r + gid + 8][ks + 2 * tig];
                a[mt][2] = *(const uint32_t*)&As[buf][r + gid][ks + 2 * tig + 8];
                a[mt][3] = *(const uint32_t*)&As[buf][r + gid + 8][ks + 2 * tig + 8];
            }
            int kb = ks >> 1;
            #pragma unroll
            for (int nt = 0; nt < 8; nt++) {
                int c = wc * 64 + nt * 8 + gid;
                b[nt][0] = Bs[buf][kb + tig][c];
                b[nt][1] = Bs[buf][kb + tig + 4][c];
            }
            #pragma unroll
            for (int mt = 0; mt < 2; mt++)
                #pragma unroll
                for (int nt = 0; nt < 8; nt++) {
                    asm volatile(
                        "mma.sync.aligned.m16n8k16.row.col.f32.f16.f16.f32 "
                        "{%0,%1,%2,%3}, {%4,%5,%6,%7}, {%8,%9}, {%0,%1,%2,%3};"
                        : "+f"(acc[mt][nt][0]), "+f"(acc[mt][nt][1]),
                          "+f"(acc[mt][nt][2]), "+f"(acc[mt][nt][3])
                        : "r"(a[mt][0]), "r"(a[mt][1]), "r"(a[mt][2]), "r"(a[mt][3]),
                          "r"(b[nt][0]), "r"(b[nt][1]));
                }
        }
        __syncthreads();
    }

    // ---- store fp16 ----
    #pragma unroll
    for (int mt = 0; mt < 2; mt++) {
        #pragma unroll
        for (int nt = 0; nt < 8; nt++) {
            int r0 = bm + wr * 32 + mt * 16 + gid;
            int cc = bn + wc * 64 + nt * 8 + tig * 2;
            if (r0 < NN) {
                __half2 h = __floats2half2_rn(acc[mt][nt][0], acc[mt][nt][1]);
                *(__half2*)(g_t16 + (size_t)r0 * 256 + cc) = h;
            }
            if (r0 + 8 < NN) {
                __half2 h = __floats2half2_rn(acc[mt][nt][2], acc[mt][nt][3]);
                *(__half2*)(g_t16 + (size_t)(r0 + 8) * 256 + cc) = h;
            }
        }
    }
}

// ---------------- aggregation: 1 warp/node, fp16 gather + fp16 writeback ----------------
__device__ __forceinline__ void acc8(float* a, uint4 v, float w) {
    __half2* h = (__half2*)&v;
    #pragma unroll
    for (int j = 0; j < 4; j++) {
        float2 f = __half22float2(h[j]);
        a[2 * j + 0] += w * f.x;
        a[2 * j + 1] += w * f.y;
    }
}

__global__ void k_agg(const float* __restrict__ bias, int relu) {
    int gw = (blockIdx.x * blockDim.x + threadIdx.x) >> 5;
    int lane = threadIdx.x & 31;
    if (gw >= NN) return;
    int n = gw;
    const uint4* t4 = (const uint4*)g_t16;   // row = 32 uint4

    float dn = g_dinv[n];
    float sw = dn * dn;
    float a[8] = {};
    acc8(a, __ldg(&t4[(size_t)n * 32 + lane]), sw);

    int beg = g_rowptr[n], end = g_rowptr[n + 1];
    int i = beg;
    for (; i + 4 <= end; i += 4) {
        int s0 = g_csr_src[i],   s1 = g_csr_src[i+1];
        int s2 = g_csr_src[i+2], s3 = g_csr_src[i+3];
        float w0 = g_csr_w[i],   w1 = g_csr_w[i+1];
        float w2 = g_csr_w[i+2], w3 = g_csr_w[i+3];
        uint4 v0 = __ldg(&t4[(size_t)s0 * 32 + lane]);
        uint4 v1 = __ldg(&t4[(size_t)s1 * 32 + lane]);
        uint4 v2 = __ldg(&t4[(size_t)s2 * 32 + lane]);
        uint4 v3 = __ldg(&t4[(size_t)s3 * 32 + lane]);
        acc8(a, v0, w0); acc8(a, v1, w1); acc8(a, v2, w2); acc8(a, v3, w3);
    }
    for (; i < end; i++) {
        int s = g_csr_src[i];
        float w = g_csr_w[i];
        acc8(a, __ldg(&t4[(size_t)s * 32 + lane]), w);
    }

    float4 b0 = ((const float4*)bias)[lane * 2];
    float4 b1 = ((const float4*)bias)[lane * 2 + 1];
    a[0] += b0.x; a[1] += b0.y; a[2] += b0.z; a[3] += b0.w;
    a[4] += b1.x; a[5] += b1.y; a[6] += b1.z; a[7] += b1.w;
    if (relu) {
        #pragma unroll
        for (int j = 0; j < 8; j++) a[j] = fmaxf(a[j], 0.f);
    }
    uint4 o;
    __half2* oh = (__half2*)&o;
    oh[0] = __floats2half2_rn(a[0], a[1]);
    oh[1] = __floats2half2_rn(a[2], a[3]);
    oh[2] = __floats2half2_rn(a[4], a[5]);
    oh[3] = __floats2half2_rn(a[6], a[7]);
    ((uint4*)g_a16)[(size_t)n * 32 + lane] = o;
}

// ---------------- fused mean-pool + classifier: one block per graph ----------------
__global__ void k_head(const int* __restrict__ batch,
                       const float* __restrict__ Wc1, const float* __restrict__ bc1,
                       const float* __restrict__ Wc2, const float* __restrict__ bc2,
                       const float* __restrict__ Wc3, const float* __restrict__ bc3,
                       float* __restrict__ out) {
    int g = blockIdx.x, t = threadIdx.x;
    __shared__ float p[256], q1[16], q2[64];
    __shared__ int slo, shi;
    if (t == 0) {
        int l = 0, r = NN;
        while (l < r) { int m = (l + r) >> 1; if (batch[m] < g) l = m + 1; else r = m; }
        slo = l;
        l = 0; r = NN;
        while (l < r) { int m = (l + r) >> 1; if (batch[m] < g + 1) l = m + 1; else r = m; }
        shi = l;
    }
    __syncthreads();
    int lo = slo, hi = shi;
    float s = 0.f;
    for (int n = lo; n < hi; n++) s += __half2float(g_a16[(size_t)n * 256 + t]);
    int cnt = hi - lo;
    float inv = (cnt > 0) ? (1.0f / (float)cnt) : 1.0f;
    p[t] = s * inv;
    __syncthreads();

    float* o1 = out;
    float* o2 = out + 256 * 16;
    float* o3 = out + 256 * 16 + 256 * 64;

    if (t < 16) {
        float v = bc1[t];
        for (int k = 0; k < 256; k++) v += p[k] * Wc1[k * 16 + t];
        q1[t] = v;
        o1[g * 16 + t] = v;
    }
    __syncthreads();
    if (t == 0) {
        float m = q1[0];
        for (int i = 1; i < 16; i++) m = fmaxf(m, q1[i]);
        float sum = 0.f;
        for (int i = 0; i < 16; i++) { q1[i] = expf(q1[i] - m); sum += q1[i]; }
        float inv2 = 1.f / sum;
        for (int i = 0; i < 16; i++) q1[i] *= inv2;
    }
    __syncthreads();
    if (t < 64) {
        float v = bc2[t];
        for (int k = 0; k < 256; k++) v += p[k] * Wc2[k * 64 + t];
        for (int k = 0; k < 16; k++) v += q1[k] * Wc2[(256 + k) * 64 + t];
        q2[t] = v;
        o2[g * 64 + t] = v;
    }
    __syncthreads();
    if (t == 0) {
        float m = q2[0];
        for (int i = 1; i < 64; i++) m = fmaxf(m, q2[i]);
        float sum = 0.f;
        for (int i = 0; i < 64; i++) { q2[i] = expf(q2[i] - m); sum += q2[i]; }
        float inv2 = 1.f / sum;
        for (int i = 0; i < 64; i++) q2[i] *= inv2;
    }
    __syncthreads();
    {
        float v = bc3[t];
        for (int k = 0; k < 256; k++) v += p[k] * Wc3[k * 256 + t];
        for (int k = 0; k < 64; k++) v += q2[k] * Wc3[(256 + k) * 256 + t];
        o3[g * 256 + t] = v;
    }
}

// ---------------- launch ----------------
extern "C" void kernel_launch(void* const* d_in, const int* in_sizes, int n_in,
                              void* d_out, int out_size) {
    const float* x     = (const float*)d_in[0];
    const int*   ei    = (const int*)d_in[1];
    const int*   batch = (const int*)d_in[2];
    const float* W1 = (const float*)d_in[3],  *b1 = (const float*)d_in[4];
    const float* W2 = (const float*)d_in[5],  *b2 = (const float*)d_in[6];
    const float* W3 = (const float*)d_in[7],  *b3 = (const float*)d_in[8];
    const float* Wc1 = (const float*)d_in[9],  *bc1 = (const float*)d_in[10];
    const float* Wc2 = (const float*)d_in[11], *bc2 = (const float*)d_in[12];
    const float* Wc3 = (const float*)d_in[13], *bc3 = (const float*)d_in[14];
    float* out = (float*)d_out;

    // graph preprocessing
    k_zero<<<(NN + 255) / 256, 256>>>();
    k_hist<<<NE / 256, 256>>>(ei);
    k_scan<<<1, 1024>>>();
    k_build<<<NE / 256, 256>>>(ei);

    // conversions (outputs are device symbols referenced inside the kernels)
    k_cvt_x<<<(int)(((size_t)NN * KP1 + 255) / 256), 256>>>(x);
    k_cvt_w<<<((KP1/2) * HID + 255) / 256, 256>>>(W1, 0, INDIM, KP1 / 2);
    k_cvt_w<<<((HID/2) * HID + 255) / 256, 256>>>(W2, 1, HID, HID / 2);
    k_cvt_w<<<((HID/2) * HID + 255) / 256, 256>>>(W3, 2, HID, HID / 2);

    dim3 gg(2, (NN + 127) / 128);  // (2, 391)
    int agg_blocks = (NN * 32 + 255) / 256;
    k_gemm_f16<<<gg, 256>>>(0);
    k_agg<<<agg_blocks, 256>>>(b1, 1);
    k_gemm_f16<<<gg, 256>>>(1);
    k_agg<<<agg_blocks, 256>>>(b2, 1);
    k_gemm_f16<<<gg, 256>>>(2);
    k_agg<<<agg_blocks, 256>>>(b3, 0);

    k_head<<<NG, 256>>>(batch, Wc1, bc1, Wc2, bc2, Wc3, bc3, out);
}

// round 11
// speedup vs baseline: 1.3400x; 1.1009x over previous
#include <cuda_runtime.h>
#include <cuda_fp16.h>
#include <stdint.h>

#define NN 50000
#define NE 800000
#define NG 256
#define INDIM 300
#define KP1 320          // x padded K (multiple of 32)
#define HID 256

// ---------------- scratch (device globals; no allocation allowed) ----------------
__device__ __align__(16) __half   g_x16[(size_t)NN * KP1];   // x in fp16, K padded
__device__ __align__(16) __half   g_t16[(size_t)NN * HID];   // transformed (h @ W), fp16
__device__ __align__(16) __half   g_a16[(size_t)NN * HID];   // aggregated output, fp16
__device__ __align__(16) uint32_t g_w1p[(KP1/2) * HID];      // W packed k-pairs (fp16x2)
__device__ __align__(16) uint32_t g_w2p[(HID/2) * HID];
__device__ __align__(16) uint32_t g_w3p[(HID/2) * HID];
__device__ float g_dinv[NN];
__device__ int   g_cnt[NN];
__device__ int   g_rowptr[NN + 1];
__device__ int   g_cursor[NN];
__device__ int   g_csr_src[NE];
__device__ float g_csr_w[NE];

// ---------------- graph preprocessing ----------------
__global__ void k_zero() {
    int i = blockIdx.x * blockDim.x + threadIdx.x;
    if (i < NN) g_cnt[i] = 0;
}

__global__ void k_hist(const int* __restrict__ ei) {
    int e = blockIdx.x * blockDim.x + threadIdx.x;
    if (e < NE) {
        int d = ei[NE + e];
        if (d >= 0 && d < NN) atomicAdd(&g_cnt[d], 1);
    }
}

__global__ void k_scan() {
    const int CH = (NN + 1023) / 1024;  // 49
    __shared__ int part[1024];
    int t = threadIdx.x;
    int begin = t * CH;
    int end = begin + CH; if (end > NN) end = NN; if (begin > NN) begin = NN;
    int s = 0;
    for (int i = begin; i < end; i++) s += g_cnt[i];
    part[t] = s;
    __syncthreads();
    if (t == 0) {
        int run = 0;
        for (int i = 0; i < 1024; i++) { int v = part[i]; part[i] = run; run += v; }
    }
    __syncthreads();
    int run = part[t];
    for (int i = begin; i < end; i++) {
        int c = g_cnt[i];
        g_rowptr[i] = run; run += c;
        g_dinv[i] = rsqrtf((float)(c + 1));
        g_cursor[i] = 0;
    }
    if (t == 1023) g_rowptr[NN] = run;
}

__global__ void k_build(const int* __restrict__ ei) {
    int e = blockIdx.x * blockDim.x + threadIdx.x;
    if (e >= NE) return;
    int s = ei[e];
    int d = ei[NE + e];
    if (s < 0 || s >= NN || d < 0 || d >= NN) return;
    int pos = g_rowptr[d] + atomicAdd(&g_cursor[d], 1);
    g_csr_src[pos] = s;
    g_csr_w[pos] = g_dinv[s] * g_dinv[d];
}

// ---------------- input conversions ----------------
__global__ void k_cvt_x(const float* __restrict__ x) {
    size_t i = (size_t)blockIdx.x * blockDim.x + threadIdx.x;
    if (i >= (size_t)NN * KP1) return;
    int col = (int)(i % KP1);
    int row = (int)(i / KP1);
    float v = (col < INDIM) ? x[(size_t)row * INDIM + col] : 0.f;
    g_x16[i] = __float2half_rn(v);
}

// pack all three weight matrices in one launch:
// out[k2][n] = (half(W[2k2][n]), half(W[2k2+1][n]))
__global__ void k_cvt_w3(const float* __restrict__ W1,
                         const float* __restrict__ W2,
                         const float* __restrict__ W3) {
    const int N1 = (KP1 / 2) * HID;   // 40960
    const int N2 = (HID / 2) * HID;   // 32768
    int i = blockIdx.x * blockDim.x + threadIdx.x;
    const float* W; uint32_t* out; int K; int j;
    if (i < N1)                { W = W1; out = g_w1p; K = INDIM; j = i; }
    else if (i < N1 + N2)      { W = W2; out = g_w2p; K = HID;   j = i - N1; }
    else if (i < N1 + 2 * N2)  { W = W3; out = g_w3p; K = HID;   j = i - N1 - N2; }
    else return;
    int n = j % HID, k2 = j / HID;
    int ka = 2 * k2, kb = 2 * k2 + 1;
    float lo = (ka < K) ? W[(size_t)ka * HID + n] : 0.f;
    float hi = (kb < K) ? W[(size_t)kb * HID + n] : 0.f;
    __half2 h = __floats2half2_rn(lo, hi);
    out[j] = *(uint32_t*)&h;
}

// ---------------- fp16 tensor-core GEMM, 2-stage cp.async pipeline ----------------
// layer: 0 -> A=g_x16 (K=KP1), W=g_w1p ; 1 -> A=g_a16, W=g_w2p ; 2 -> A=g_a16, W=g_w3p
__device__ __forceinline__ void cp16(uint32_t dst, const void* src, int srcbytes) {
    asm volatile("cp.async.cg.shared.global [%0], [%1], 16, %2;\n"
                 :: "r"(dst), "l"(src), "r"(srcbytes));
}
__device__ __forceinline__ void cp_commit() {
    asm volatile("cp.async.commit_group;\n");
}
__device__ __forceinline__ void cp_wait1() {
    asm volatile("cp.async.wait_group 1;\n");
}

__global__ void __launch_bounds__(256) k_gemm_f16(int layer) {
    const __half* A = (layer == 0) ? g_x16 : g_a16;
    const uint32_t* Bpk = (layer == 0) ? g_w1p : (layer == 1) ? g_w2p : g_w3p;
    const int K = (layer == 0) ? KP1 : HID;

    __shared__ __align__(16) __half   As[2][128][40];    // [buf][m][k], pad 40
    __shared__ __align__(16) uint32_t Bs[2][16][136];    // [buf][k2][n], pad 136

    int bm = blockIdx.y * 128, bn = blockIdx.x * 128;
    int tid = threadIdx.x;
    int wid = tid >> 5, lane = tid & 31;
    int wr = wid >> 1, wc = wid & 1;
    int gid = lane >> 2, tig = lane & 3;

    int a_row0 = tid >> 2, a_k80 = (tid & 3) << 3;
    int a_row1 = (tid + 256) >> 2, a_k81 = ((tid + 256) & 3) << 3;
    int b_k20 = tid >> 5, b_n40 = (tid & 31) << 2;
    int b_k21 = (tid + 256) >> 5, b_n41 = ((tid + 256) & 31) << 2;

    float acc[2][8][4];
    #pragma unroll
    for (int i = 0; i < 2; i++)
        #pragma unroll
        for (int j = 0; j < 8; j++)
            #pragma unroll
            for (int l = 0; l < 4; l++) acc[i][j][l] = 0.f;

    int T = K >> 5;

    auto load_tile = [&](int tile, int buf) {
        int k0 = tile << 5;
        {
            int grow = bm + a_row0;
            int bytes = (grow < NN) ? 16 : 0;
            const __half* src = (bytes > 0) ? (A + (size_t)grow * K + k0 + a_k80) : A;
            cp16((uint32_t)__cvta_generic_to_shared(&As[buf][a_row0][a_k80]), src, bytes);
        }
        {
            int grow = bm + a_row1;
            int bytes = (grow < NN) ? 16 : 0;
            const __half* src = (bytes > 0) ? (A + (size_t)grow * K + k0 + a_k81) : A;
            cp16((uint32_t)__cvta_generic_to_shared(&As[buf][a_row1][a_k81]), src, bytes);
        }
        int k20 = k0 >> 1;
        cp16((uint32_t)__cvta_generic_to_shared(&Bs[buf][b_k20][b_n40]),
             Bpk + (size_t)(k20 + b_k20) * 256 + bn + b_n40, 16);
        cp16((uint32_t)__cvta_generic_to_shared(&Bs[buf][b_k21][b_n41]),
             Bpk + (size_t)(k20 + b_k21) * 256 + bn + b_n41, 16);
    };

    load_tile(0, 0);
    cp_commit();

    for (int it = 0; it < T; it++) {
        if (it + 1 < T) load_tile(it + 1, (it + 1) & 1);
        cp_commit();
        cp_wait1();
        __syncthreads();

        int buf = it & 1;
        #pragma unroll
        for (int ks = 0; ks < 32; ks += 16) {
            uint32_t a[2][4], b[8][2];
            #pragma unroll
            for (int mt = 0; mt < 2; mt++) {
                int r = wr * 32 + mt * 16;
                a[mt][0] = *(const uint32_t*)&As[buf][r + gid][ks + 2 * tig];
                a[mt][1] = *(const uint32_t*)&As[buf][r + gid + 8][ks + 2 * tig];
                a[mt][2] = *(const uint32_t*)&As[buf][r + gid][ks + 2 * tig + 8];
                a[mt][3] = *(const uint32_t*)&As[buf][r + gid + 8][ks + 2 * tig + 8];
            }
            int kb = ks >> 1;
            #pragma unroll
            for (int nt = 0; nt < 8; nt++) {
                int c = wc * 64 + nt * 8 + gid;
                b[nt][0] = Bs[buf][kb + tig][c];
                b[nt][1] = Bs[buf][kb + tig + 4][c];
            }
            #pragma unroll
            for (int mt = 0; mt < 2; mt++)
                #pragma unroll
                for (int nt = 0; nt < 8; nt++) {
                    asm volatile(
                        "mma.sync.aligned.m16n8k16.row.col.f32.f16.f16.f32 "
                        "{%0,%1,%2,%3}, {%4,%5,%6,%7}, {%8,%9}, {%0,%1,%2,%3};"
                        : "+f"(acc[mt][nt][0]), "+f"(acc[mt][nt][1]),
                          "+f"(acc[mt][nt][2]), "+f"(acc[mt][nt][3])
                        : "r"(a[mt][0]), "r"(a[mt][1]), "r"(a[mt][2]), "r"(a[mt][3]),
                          "r"(b[nt][0]), "r"(b[nt][1]));
                }
        }
        __syncthreads();
    }

    #pragma unroll
    for (int mt = 0; mt < 2; mt++) {
        #pragma unroll
        for (int nt = 0; nt < 8; nt++) {
            int r0 = bm + wr * 32 + mt * 16 + gid;
            int cc = bn + wc * 64 + nt * 8 + tig * 2;
            if (r0 < NN) {
                __half2 h = __floats2half2_rn(acc[mt][nt][0], acc[mt][nt][1]);
                *(__half2*)(g_t16 + (size_t)r0 * 256 + cc) = h;
            }
            if (r0 + 8 < NN) {
                __half2 h = __floats2half2_rn(acc[mt][nt][2], acc[mt][nt][3]);
                *(__half2*)(g_t16 + (size_t)(r0 + 8) * 256 + cc) = h;
            }
        }
    }
}

// ---------------- aggregation: 1 warp/node, fp16 gather + fp16 writeback ----------------
__device__ __forceinline__ void acc8(float* a, uint4 v, float w) {
    __half2* h = (__half2*)&v;
    #pragma unroll
    for (int j = 0; j < 4; j++) {
        float2 f = __half22float2(h[j]);
        a[2 * j + 0] += w * f.x;
        a[2 * j + 1] += w * f.y;
    }
}

__global__ void k_agg(const float* __restrict__ bias, int relu) {
    int gw = (blockIdx.x * blockDim.x + threadIdx.x) >> 5;
    int lane = threadIdx.x & 31;
    if (gw >= NN) return;
    int n = gw;
    const uint4* t4 = (const uint4*)g_t16;

    float dn = g_dinv[n];
    float sw = dn * dn;
    float a[8] = {};
    acc8(a, __ldg(&t4[(size_t)n * 32 + lane]), sw);

    int beg = g_rowptr[n], end = g_rowptr[n + 1];
    int i = beg;
    for (; i + 4 <= end; i += 4) {
        int s0 = g_csr_src[i],   s1 = g_csr_src[i+1];
        int s2 = g_csr_src[i+2], s3 = g_csr_src[i+3];
        float w0 = g_csr_w[i],   w1 = g_csr_w[i+1];
        float w2 = g_csr_w[i+2], w3 = g_csr_w[i+3];
        uint4 v0 = __ldg(&t4[(size_t)s0 * 32 + lane]);
        uint4 v1 = __ldg(&t4[(size_t)s1 * 32 + lane]);
        uint4 v2 = __ldg(&t4[(size_t)s2 * 32 + lane]);
        uint4 v3 = __ldg(&t4[(size_t)s3 * 32 + lane]);
        acc8(a, v0, w0); acc8(a, v1, w1); acc8(a, v2, w2); acc8(a, v3, w3);
    }
    for (; i < end; i++) {
        int s = g_csr_src[i];
        float w = g_csr_w[i];
        acc8(a, __ldg(&t4[(size_t)s * 32 + lane]), w);
    }

    float4 b0 = ((const float4*)bias)[lane * 2];
    float4 b1 = ((const float4*)bias)[lane * 2 + 1];
    a[0] += b0.x; a[1] += b0.y; a[2] += b0.z; a[3] += b0.w;
    a[4] += b1.x; a[5] += b1.y; a[6] += b1.z; a[7] += b1.w;
    if (relu) {
        #pragma unroll
        for (int j = 0; j < 8; j++) a[j] = fmaxf(a[j], 0.f);
    }
    uint4 o;
    __half2* oh = (__half2*)&o;
    oh[0] = __floats2half2_rn(a[0], a[1]);
    oh[1] = __floats2half2_rn(a[2], a[3]);
    oh[2] = __floats2half2_rn(a[4], a[5]);
    oh[3] = __floats2half2_rn(a[6], a[7]);
    ((uint4*)g_a16)[(size_t)n * 32 + lane] = o;
}

// ---------------- fused mean-pool + classifier ----------------
__global__ void k_head(const int* __restrict__ batch,
                       const float* __restrict__ Wc1, const float* __restrict__ bc1,
                       const float* __restrict__ Wc2, const float* __restrict__ bc2,
                       const float* __restrict__ Wc3, const float* __restrict__ bc3,
                       float* __restrict__ out) {
    int g = blockIdx.x, t = threadIdx.x;
    __shared__ float p[256], q1[16], q2[64];
    __shared__ int slo, shi;
    if (t == 0) {
        int l = 0, r = NN;
        while (l < r) { int m = (l + r) >> 1; if (batch[m] < g) l = m + 1; else r = m; }
        slo = l;
        l = 0; r = NN;
        while (l < r) { int m = (l + r) >> 1; if (batch[m] < g + 1) l = m + 1; else r = m; }
        shi = l;
    }
    __syncthreads();
    int lo = slo, hi = shi;
    float s = 0.f;
    for (int n = lo; n < hi; n++) s += __half2float(g_a16[(size_t)n * 256 + t]);
    int cnt = hi - lo;
    float inv = (cnt > 0) ? (1.0f / (float)cnt) : 1.0f;
    p[t] = s * inv;
    __syncthreads();

    float* o1 = out;
    float* o2 = out + 256 * 16;
    float* o3 = out + 256 * 16 + 256 * 64;

    if (t < 16) {
        float v = bc1[t];
        for (int k = 0; k < 256; k++) v += p[k] * Wc1[k * 16 + t];
        q1[t] = v;
        o1[g * 16 + t] = v;
    }
    __syncthreads();
    if (t == 0) {
        float m = q1[0];
        for (int i = 1; i < 16; i++) m = fmaxf(m, q1[i]);
        float sum = 0.f;
        for (int i = 0; i < 16; i++) { q1[i] = expf(q1[i] - m); sum += q1[i]; }
        float inv2 = 1.f / sum;
        for (int i = 0; i < 16; i++) q1[i] *= inv2;
    }
    __syncthreads();
    if (t < 64) {
        float v = bc2[t];
        for (int k = 0; k < 256; k++) v += p[k] * Wc2[k * 64 + t];
        for (int k = 0; k < 16; k++) v += q1[k] * Wc2[(256 + k) * 64 + t];
        q2[t] = v;
        o2[g * 64 + t] = v;
    }
    __syncthreads();
    if (t == 0) {
        float m = q2[0];
        for (int i = 1; i < 64; i++) m = fmaxf(m, q2[i]);
        float sum = 0.f;
        for (int i = 0; i < 64; i++) { q2[i] = expf(q2[i] - m); sum += q2[i]; }
        float inv2 = 1.f / sum;
        for (int i = 0; i < 64; i++) q2[i] *= inv2;
    }
    __syncthreads();
    {
        float v = bc3[t];
        for (int k = 0; k < 256; k++) v += p[k] * Wc3[k * 256 + t];
        for (int k = 0; k < 64; k++) v += q2[k] * Wc3[(256 + k) * 256 + t];
        o3[g * 256 + t] = v;
    }
}

// ---------------- launch (stream-forked: CSR chain || conversions+gemm1) ----------------
extern "C" void kernel_launch(void* const* d_in, const int* in_sizes, int n_in,
                              void* d_out, int out_size) {
    const float* x     = (const float*)d_in[0];
    const int*   ei    = (const int*)d_in[1];
    const int*   batch = (const int*)d_in[2];
    const float* W1 = (const float*)d_in[3],  *b1 = (const float*)d_in[4];
    const float* W2 = (const float*)d_in[5],  *b2 = (const float*)d_in[6];
    const float* W3 = (const float*)d_in[7],  *b3 = (const float*)d_in[8];
    const float* Wc1 = (const float*)d_in[9],  *bc1 = (const float*)d_in[10];
    const float* Wc2 = (const float*)d_in[11], *bc2 = (const float*)d_in[12];
    const float* Wc3 = (const float*)d_in[13], *bc3 = (const float*)d_in[14];
    float* out = (float*)d_out;

    // lazily created once on the (uncaptured) correctness call; reused during capture
    static cudaStream_t s2 = nullptr;
    static cudaEvent_t evf = nullptr, evj = nullptr;
    if (s2 == nullptr) {
        cudaStreamCreateWithFlags(&s2, cudaStreamNonBlocking);
        cudaEventCreateWithFlags(&evf, cudaEventDisableTiming);
        cudaEventCreateWithFlags(&evj, cudaEventDisableTiming);
    }

    dim3 gg(2, (NN + 127) / 128);  // (2, 391)
    int agg_blocks = (NN * 32 + 255) / 256;
    const int NW = (KP1 / 2) * HID + 2 * (HID / 2) * HID;  // merged cvt_w elems

    // fork: s2 branch does conversions + layer-1 GEMM (independent of graph CSR)
    cudaEventRecord(evf, 0);
    cudaStreamWaitEvent(s2, evf, 0);

    // default stream: CSR chain
    k_zero<<<(NN + 255) / 256, 256>>>();
    k_hist<<<NE / 256, 256>>>(ei);
    k_scan<<<1, 1024>>>();
    k_build<<<NE / 256, 256>>>(ei);

    // s2 branch
    k_cvt_x<<<(int)(((size_t)NN * KP1 + 255) / 256), 256, 0, s2>>>(x);
    k_cvt_w3<<<(NW + 255) / 256, 256, 0, s2>>>(W1, W2, W3);
    k_gemm_f16<<<gg, 256, 0, s2>>>(0);

    // join
    cudaEventRecord(evj, s2);
    cudaStreamWaitEvent(0, evj, 0);

    // rest strictly ordered on default stream
    k_agg<<<agg_blocks, 256>>>(b1, 1);
    k_gemm_f16<<<gg, 256>>>(1);
    k_agg<<<agg_blocks, 256>>>(b2, 1);
    k_gemm_f16<<<gg, 256>>>(2);
    k_agg<<<agg_blocks, 256>>>(b3, 0);

    k_head<<<NG, 256>>>(batch, Wc1, bc1, Wc2, bc2, Wc3, bc3, out);
}